// round 13
// baseline (speedup 1.0000x reference)
#include <cuda_runtime.h>
#include <math.h>

#define N 8192
#define D 10
#define DD (D * D)
#define TILE 256
#define NT (N / TILE)     // 32 tiles
#define PAD 11
#define NSB (TILE / 32)   // 8 warps / sub-blocks per tile

// ---- persistent device scratch (no allocation) ----
__device__ float              g_H[NT * DD];
__device__ unsigned int       g_hflag[NT];  // monotone epoch flags
__device__ long long          g_sum  = 0;   // fixed-point accumulator (2^-32)
__device__ unsigned long long g_ctr1 = 0;   // arrival tickets (monotone)
__device__ unsigned long long g_ctr2 = 0;   // finish tickets (monotone)

__device__ __forceinline__ float ex2(float x) {
    float y;
    asm("ex2.approx.ftz.f32 %0, %1;" : "=f"(y) : "f"(x));
    return y;
}
// fast softplus: max(x,0) + log(1 + exp(-|x|)) with fast intrinsics
__device__ __forceinline__ float softplus_f(float x) {
    return fmaxf(x, 0.f) + __logf(1.f + __expf(-fabsf(x)));
}
__device__ __forceinline__ float decodeT(const int* Tp) {
    int b = *Tp;
    if (b >= 0 && b < (1 << 23)) return (float)b;  // int32 T
    return __int_as_float(b);                      // float32 T
}

__global__ void __launch_bounds__(TILE)
hawkes_fused(const float* __restrict__ t, const int* __restrict__ et,
             const float* __restrict__ mu, const float* __restrict__ la,
             const float* __restrict__ lb, const int* __restrict__ Tp,
             float* __restrict__ out) {
    const int tid = threadIdx.x;
    const int it  = blockIdx.x;

    __shared__ int   es[TILE];
    __shared__ float b2s[DD], abt[DD], alphas[DD], mus[D];
    __shared__ float F[TILE * PAD], G[TILE * PAD];
    __shared__ float subH[NSB][DD];     // per-warp H, then inclusive prefix
    __shared__ float Psm[D * PAD];
    __shared__ float trefs[NT];
    __shared__ double red[NSB];
    __shared__ unsigned long long tick_s;

    // ---- ticket at entry (epoch known early; overlaps loads) ----
    if (tid == 0) tick_s = atomicAdd(&g_ctr1, 1ULL);

    // ---- tables + tile load + tref gather + subH zero ----
    if (tid < DD) {
        float a = softplus_f(la[tid]);
        float b = softplus_f(lb[tid]);
        alphas[tid] = a;
        b2s[tid]    = b * 1.4426950408889634f;
        abt[tid]    = a * b;
    }
    if (tid >= 128 && tid < 128 + D) mus[tid - 128] = softplus_f(mu[tid - 128]);
    if (tid >= 160 && tid < 160 + NT) trefs[tid - 160] = t[(tid - 160) * TILE + TILE - 1];
    {
        float* z = &subH[0][0];
        for (int e = tid; e < NSB * DD; e += TILE) z[e] = 0.f;
    }

    const int   i  = it * TILE + tid;
    const float ti = t[i];         // register only
    const int   ei = et[i];
    es[tid] = ei;
    __syncthreads();

    const float tref = trefs[it];
    const float dtj  = ti - tref;   // <= 0

    // G_j[k] = 2^(b2[k][e_j]*(t_j - tref)) <= 1  (kept in registers + stored)
    float g[D];
#pragma unroll
    for (int k = 0; k < D; k++) {
        g[k] = ex2(b2s[k * D + ei] * dtj);
        G[tid * PAD + k] = g[k];
    }

    // ---- per-warp H via match_any + integer redux (deterministic) ----
    {
        const int w = tid >> 5, lane = tid & 31;
        unsigned grp = __match_any_sync(0xffffffffu, ei);
        int leader = __ffs(grp) - 1;
#pragma unroll
        for (int k = 0; k < D; k++) {
            int gi = __float2int_rn(g[k] * 33554432.f);     // 2^25
            int s  = __reduce_add_sync(grp, gi);
            if (lane == leader)
                subH[w][ei * D + k] = (float)s * 2.9802322387695312e-08f; // 2^-25
        }
    }
    __syncthreads();

    // ---- inclusive prefix + EARLY publish of full-tile H, then flag ----
    if (tid < DD) {
        float run = subH[0][tid];
#pragma unroll
        for (int sb = 1; sb < NSB; sb++) { run += subH[sb][tid]; subH[sb][tid] = run; }
        g_H[it * DD + tid] = run;
        __threadfence();   // release H
    }
    __syncthreads();
    const unsigned int epoch1 = (unsigned int)(tick_s / NT) + 1u;
    if (tid == 0) atomicExch(&g_hflag[it], epoch1);

    // early non-blocking probe of predecessor flags (overlaps local work)
    unsigned int f0 = epoch1;
    if (tid < it) f0 = *(volatile unsigned int*)&g_hflag[tid];

    // ---- local work AFTER publish (F rows are thread-private: no barrier) ----
#pragma unroll
    for (int m = 0; m < D; m++)
        F[tid * PAD + m] = abt[ei * D + m] * ex2(-b2s[ei * D + m] * dtj);

    // in-warp strict triangle
    float tri = 0.f;
    {
        const int base = tid & ~31;
        const int lid  = tid & 31;
#pragma unroll
        for (int jj = 0; jj < 31; jj++) {
            if (jj < lid) {
                int j = base + jj;
                tri = fmaf(F[tid * PAD + es[j]], G[j * PAD + ei], tri);
            }
        }
    }

    // cross-sub-block (prefix at sb-1)
    float crossSub = 0.f;
    {
        const int sb = tid >> 5;
        if (sb > 0) {
#pragma unroll
            for (int m = 0; m < D; m++)
                crossSub = fmaf(F[tid * PAD + m], subH[sb - 1][m * D + ei], crossSub);
        }
    }

    // contrib term (independent of P)
    const float Tf = decodeT(Tp);
    const float dT = Tf - ti;
    float contrib = 0.f;
#pragma unroll
    for (int d = 0; d < D; d++)
        contrib += alphas[d * D + ei] * (1.f - ex2(-b2s[d * D + ei] * dT));

    // ---- spin on predecessors (only if the early probe missed) ----
    if (tid < it && f0 < epoch1) {
        while (*(volatile unsigned int*)&g_hflag[tid] < epoch1)
            __nanosleep(32);
    }
    __syncthreads();
    __threadfence();   // acquire H

    // ---- cross-tile P (direct sum): fully unrolled, 31 loads in flight ----
    if (tid < DD) {
        const int m = tid / D, kk = tid % D;
        const float b2 = b2s[kk * D + m];
        float h[NT - 1];
#pragma unroll
        for (int s = 0; s < NT - 1; s++)
            h[s] = (s < it) ? __ldcg(&g_H[s * DD + tid]) : 0.f;
        float acc = 0.f;
#pragma unroll
        for (int s = 0; s < NT - 1; s++) {
            float tr = (s < it) ? trefs[s] : tref;   // pad: ex2(0)=1, h=0
            acc = fmaf(h[s], ex2(-b2 * (tref - tr)), acc);
        }
        Psm[m * PAD + kk] = acc;
    }
    __syncthreads();

    float crossTile = 0.f;
    if (it > 0) {
#pragma unroll
        for (int m = 0; m < D; m++)
            crossTile = fmaf(F[tid * PAD + m], Psm[m * PAD + ei], crossTile);
    }

    // ---- finalize per event: float in-warp, double across warps ----
    const float inten = mus[ei] + tri + crossSub + crossTile;
    float vf = __logf(inten) - contrib;
#pragma unroll
    for (int off = 16; off > 0; off >>= 1)
        vf += __shfl_down_sync(0xffffffffu, vf, off);
    if ((tid & 31) == 0) red[tid >> 5] = (double)vf;
    __syncthreads();

    if (tid == 0) {
        double bs = 0.0;
#pragma unroll
        for (int w = 0; w < NSB; w++) bs += red[w];
        long long q = __double2ll_rn(bs * 4294967296.0);
        atomicAdd((unsigned long long*)&g_sum, (unsigned long long)q);
        __threadfence();
        unsigned long long t2 = atomicAdd(&g_ctr2, 1ULL);
        if ((t2 % NT) == (NT - 1)) {
            __threadfence();
            long long tot = (long long)atomicExch((unsigned long long*)&g_sum, 0ULL);
            double s = (double)tot / 4294967296.0;
            double musum = 0.0;
#pragma unroll
            for (int d = 0; d < D; d++) musum += (double)mus[d];
            out[0] = (float)(s - musum * (double)Tf);
        }
    }
}

extern "C" void kernel_launch(void* const* d_in, const int* in_sizes, int n_in,
                              void* d_out, int out_size) {
    const float* t  = (const float*)d_in[0];
    const int*   et = (const int*)d_in[1];
    const float* mu = (const float*)d_in[2];
    const float* la = (const float*)d_in[3];
    const float* lb = (const float*)d_in[4];
    const int*   Tp = (const int*)d_in[5];

    hawkes_fused<<<NT, TILE>>>(t, et, mu, la, lb, Tp, (float*)d_out);
}

// round 14
// speedup vs baseline: 1.3145x; 1.3145x over previous
#include <cuda_runtime.h>
#include <math.h>

#define N 8192
#define D 10
#define DD (D * D)
#define TILE 256
#define NT (N / TILE)     // 32 tiles
#define PAD 11
#define NSB (TILE / 32)   // 8 warps / sub-blocks per tile

// ---- persistent device scratch (no allocation) ----
__device__ float              g_H[NT * DD];
__device__ unsigned int       g_hflag[NT];  // monotone epoch flags
__device__ long long          g_sum  = 0;   // fixed-point accumulator (2^-32)
__device__ unsigned long long g_ctr1 = 0;   // arrival tickets (monotone)
__device__ unsigned long long g_ctr2 = 0;   // finish tickets (monotone)

__device__ __forceinline__ float ex2(float x) {
    float y;
    asm("ex2.approx.ftz.f32 %0, %1;" : "=f"(y) : "f"(x));
    return y;
}
// fast softplus: max(x,0) + log(1 + exp(-|x|)) with fast intrinsics
__device__ __forceinline__ float softplus_f(float x) {
    return fmaxf(x, 0.f) + __logf(1.f + __expf(-fabsf(x)));
}
__device__ __forceinline__ float decodeT(const int* Tp) {
    int b = *Tp;
    if (b >= 0 && b < (1 << 23)) return (float)b;  // int32 T
    return __int_as_float(b);                      // float32 T
}

__global__ void __launch_bounds__(TILE)
hawkes_fused(const float* __restrict__ t, const int* __restrict__ et,
             const float* __restrict__ mu, const float* __restrict__ la,
             const float* __restrict__ lb, const int* __restrict__ Tp,
             float* __restrict__ out) {
    const int tid = threadIdx.x;
    const int it  = blockIdx.x;

    __shared__ int   es[TILE];
    __shared__ float b2s[DD], abt[DD], alphas[DD], mus[D];
    __shared__ float F[TILE * PAD], G[TILE * PAD];
    __shared__ float subH[NSB][DD];         // per-warp H, then inclusive prefix
    __shared__ unsigned int masks[NSB][D];  // per-(warp, m) membership bits
    __shared__ float Psm[D * PAD];
    __shared__ float trefs[NT];
    __shared__ double red[NSB];
    __shared__ unsigned long long tick_s;

    // ---- ticket at entry (epoch known early; overlaps loads) ----
    if (tid == 0) tick_s = atomicAdd(&g_ctr1, 1ULL);

    // ---- tables + tile load + tref gather ----
    if (tid < DD) {
        float a = softplus_f(la[tid]);
        float b = softplus_f(lb[tid]);
        alphas[tid] = a;
        b2s[tid]    = b * 1.4426950408889634f;
        abt[tid]    = a * b;
    }
    if (tid >= 128 && tid < 128 + D) mus[tid - 128] = softplus_f(mu[tid - 128]);
    if (tid >= 160 && tid < 160 + NT) trefs[tid - 160] = t[(tid - 160) * TILE + TILE - 1];

    const int   i  = it * TILE + tid;
    const float ti = t[i];         // register only; no smem staging
    const int   ei = et[i];
    es[tid] = ei;
    __syncthreads();

    const float tref = trefs[it];
    const float dtj  = ti - tref;   // <= 0

    // G_j[k] = 2^(b2[k][e_j]*(t_j - tref)) <= 1
#pragma unroll
    for (int k = 0; k < D; k++)
        G[tid * PAD + k] = ex2(b2s[k * D + ei] * dtj);

    // per-warp membership bitmasks
    {
        const int lane = tid & 31, w = tid >> 5;
#pragma unroll
        for (int m = 0; m < D; m++) {
            unsigned b = __ballot_sync(0xffffffffu, ei == m);
            if (lane == m) masks[w][m] = b;
        }
    }
    __syncthreads();

    // ---- subH[sb][m][k] = sum_{j in sb, e_j=m} G_j[k] (mask-predicated, j-order) ----
    for (int e = tid; e < NSB * DD; e += TILE) {
        const int sb = e / DD, r = e - sb * DD;
        const int m = r / D, kk = r - m * D;
        const unsigned msk = masks[sb][m];
        const int j0 = sb * 32;
        float acc = 0.f;
#pragma unroll
        for (int j = 0; j < 32; j++)
            acc += (msk & (1u << j)) ? G[(j0 + j) * PAD + kk] : 0.f;
        subH[sb][r] = acc;
    }
    __syncthreads();

    // ---- inclusive prefix + EARLY publish of full-tile H, then flag ----
    if (tid < DD) {
        float run = subH[0][tid];
#pragma unroll
        for (int sb = 1; sb < NSB; sb++) { run += subH[sb][tid]; subH[sb][tid] = run; }
        g_H[it * DD + tid] = run;
        __threadfence();   // release H
    }
    __syncthreads();
    const unsigned int epoch1 = (unsigned int)(tick_s / NT) + 1u;
    if (tid == 0) atomicExch(&g_hflag[it], epoch1);

    // early non-blocking probe of predecessor flags (overlaps local work)
    unsigned int f0 = epoch1;
    if (tid < it) f0 = *(volatile unsigned int*)&g_hflag[tid];

    // ---- local work AFTER publish (F rows are thread-private: no barrier) ----
#pragma unroll
    for (int m = 0; m < D; m++)
        F[tid * PAD + m] = abt[ei * D + m] * ex2(-b2s[ei * D + m] * dtj);

    // in-warp strict triangle
    float tri = 0.f;
    {
        const int base = tid & ~31;
        const int lid  = tid & 31;
#pragma unroll
        for (int jj = 0; jj < 31; jj++) {
            if (jj < lid) {
                int j = base + jj;
                tri = fmaf(F[tid * PAD + es[j]], G[j * PAD + ei], tri);
            }
        }
    }

    // cross-sub-block (prefix at sb-1)
    float crossSub = 0.f;
    {
        const int sb = tid >> 5;
        if (sb > 0) {
#pragma unroll
            for (int m = 0; m < D; m++)
                crossSub = fmaf(F[tid * PAD + m], subH[sb - 1][m * D + ei], crossSub);
        }
    }

    // contrib term (independent of P)
    const float Tf = decodeT(Tp);
    const float dT = Tf - ti;
    float contrib = 0.f;
#pragma unroll
    for (int d = 0; d < D; d++)
        contrib += alphas[d * D + ei] * (1.f - ex2(-b2s[d * D + ei] * dT));

    // ---- spin on predecessors (only if the early probe missed) ----
    if (tid < it && f0 < epoch1) {
        while (*(volatile unsigned int*)&g_hflag[tid] < epoch1)
            __nanosleep(32);
    }
    __syncthreads();
    __threadfence();   // acquire H

    // ---- cross-tile P (direct sum): fully unrolled, 31 loads in flight ----
    if (tid < DD) {
        const int m = tid / D, kk = tid % D;
        const float b2 = b2s[kk * D + m];
        float h[NT - 1];
#pragma unroll
        for (int s = 0; s < NT - 1; s++)
            h[s] = (s < it) ? __ldcg(&g_H[s * DD + tid]) : 0.f;
        float acc = 0.f;
#pragma unroll
        for (int s = 0; s < NT - 1; s++) {
            float tr = (s < it) ? trefs[s] : tref;   // pad: ex2(0)=1, h=0
            acc = fmaf(h[s], ex2(-b2 * (tref - tr)), acc);
        }
        Psm[m * PAD + kk] = acc;
    }
    __syncthreads();

    float crossTile = 0.f;
    if (it > 0) {
#pragma unroll
        for (int m = 0; m < D; m++)
            crossTile = fmaf(F[tid * PAD + m], Psm[m * PAD + ei], crossTile);
    }

    // ---- finalize per event: float in-warp, double across warps ----
    const float inten = mus[ei] + tri + crossSub + crossTile;
    float vf = __logf(inten) - contrib;
#pragma unroll
    for (int off = 16; off > 0; off >>= 1)
        vf += __shfl_down_sync(0xffffffffu, vf, off);
    if ((tid & 31) == 0) red[tid >> 5] = (double)vf;
    __syncthreads();

    if (tid == 0) {
        double bs = 0.0;
#pragma unroll
        for (int w = 0; w < NSB; w++) bs += red[w];
        long long q = __double2ll_rn(bs * 4294967296.0);
        atomicAdd((unsigned long long*)&g_sum, (unsigned long long)q);
        __threadfence();
        unsigned long long t2 = atomicAdd(&g_ctr2, 1ULL);
        if ((t2 % NT) == (NT - 1)) {
            __threadfence();
            long long tot = (long long)atomicExch((unsigned long long*)&g_sum, 0ULL);
            double s = (double)tot / 4294967296.0;
            double musum = 0.0;
#pragma unroll
            for (int d = 0; d < D; d++) musum += (double)mus[d];
            out[0] = (float)(s - musum * (double)Tf);
        }
    }
}

extern "C" void kernel_launch(void* const* d_in, const int* in_sizes, int n_in,
                              void* d_out, int out_size) {
    const float* t  = (const float*)d_in[0];
    const int*   et = (const int*)d_in[1];
    const float* mu = (const float*)d_in[2];
    const float* la = (const float*)d_in[3];
    const float* lb = (const float*)d_in[4];
    const int*   Tp = (const int*)d_in[5];

    hawkes_fused<<<NT, TILE>>>(t, et, mu, la, lb, Tp, (float*)d_out);
}

// round 15
// speedup vs baseline: 1.3409x; 1.0201x over previous
#include <cuda_runtime.h>
#include <math.h>

#define N 8192
#define D 10
#define DD (D * D)
#define TILE 256
#define NT (N / TILE)     // 32 tiles
#define PAD 11
#define NSB (TILE / 32)   // 8 warps / sub-blocks per tile

// ---- persistent device scratch (no allocation) ----
__device__ float              g_H[NT * DD];
__device__ unsigned int       g_hflag[NT];  // monotone epoch flags
__device__ long long          g_sum  = 0;   // fixed-point accumulator (2^-32)
__device__ unsigned long long g_ctr1 = 0;   // arrival tickets (monotone)
__device__ unsigned long long g_ctr2 = 0;   // finish tickets (monotone)

__device__ __forceinline__ float ex2(float x) {
    float y;
    asm("ex2.approx.ftz.f32 %0, %1;" : "=f"(y) : "f"(x));
    return y;
}
// fast softplus: max(x,0) + log(1 + exp(-|x|)) with fast intrinsics
__device__ __forceinline__ float softplus_f(float x) {
    return fmaxf(x, 0.f) + __logf(1.f + __expf(-fabsf(x)));
}
__device__ __forceinline__ float decodeT(const int* Tp) {
    int b = *Tp;
    if (b >= 0 && b < (1 << 23)) return (float)b;  // int32 T
    return __int_as_float(b);                      // float32 T
}

__global__ void __launch_bounds__(TILE)
hawkes_fused(const float* __restrict__ t, const int* __restrict__ et,
             const float* __restrict__ mu, const float* __restrict__ la,
             const float* __restrict__ lb, const int* __restrict__ Tp,
             float* __restrict__ out) {
    const int tid = threadIdx.x;
    const int it  = blockIdx.x;

    __shared__ int   es[TILE];
    __shared__ float b2s[DD], abt[DD], alphas[DD], mus[D];
    __shared__ float F[TILE * PAD], G[TILE * PAD];
    __shared__ float subH[NSB][DD];         // per-warp H, then inclusive prefix
    __shared__ unsigned int masks[NSB][D];  // per-(warp, m) membership bits
    __shared__ float Psm[D * PAD];
    __shared__ float trefs[NT];
    __shared__ double red[NSB];
    __shared__ unsigned long long tick_s;

    // ---- ticket at entry (epoch known early; overlaps loads) ----
    if (tid == 0) tick_s = atomicAdd(&g_ctr1, 1ULL);

    // ---- tables + tile load + tref gather ----
    if (tid < DD) {
        float a = softplus_f(la[tid]);
        float b = softplus_f(lb[tid]);
        alphas[tid] = a;
        b2s[tid]    = b * 1.4426950408889634f;
        abt[tid]    = a * b;
    }
    if (tid >= 128 && tid < 128 + D) mus[tid - 128] = softplus_f(mu[tid - 128]);
    if (tid >= 160 && tid < 160 + NT) trefs[tid - 160] = t[(tid - 160) * TILE + TILE - 1];

    const int   i  = it * TILE + tid;
    const float ti = t[i];         // register only; no smem staging
    const int   ei = et[i];
    es[tid] = ei;
    __syncthreads();

    const float tref = trefs[it];
    const float dtj  = ti - tref;   // <= 0

    // G_j[k] = 2^(b2[k][e_j]*(t_j - tref)) <= 1
#pragma unroll
    for (int k = 0; k < D; k++)
        G[tid * PAD + k] = ex2(b2s[k * D + ei] * dtj);

    // per-warp membership bitmasks
    {
        const int lane = tid & 31, w = tid >> 5;
#pragma unroll
        for (int m = 0; m < D; m++) {
            unsigned b = __ballot_sync(0xffffffffu, ei == m);
            if (lane == m) masks[w][m] = b;
        }
    }
    __syncthreads();

    // ---- subH[sb][m][k] = sum_{j in sb, e_j=m} G_j[k] (mask-predicated, j-order) ----
    for (int e = tid; e < NSB * DD; e += TILE) {
        const int sb = e / DD, r = e - sb * DD;
        const int m = r / D, kk = r - m * D;
        const unsigned msk = masks[sb][m];
        const int j0 = sb * 32;
        float acc = 0.f;
#pragma unroll
        for (int j = 0; j < 32; j++)
            acc += (msk & (1u << j)) ? G[(j0 + j) * PAD + kk] : 0.f;
        subH[sb][r] = acc;
    }
    __syncthreads();

    // ---- inclusive prefix + EARLY publish of full-tile H, then flag ----
    if (tid < DD) {
        float run = subH[0][tid];
#pragma unroll
        for (int sb = 1; sb < NSB; sb++) { run += subH[sb][tid]; subH[sb][tid] = run; }
        g_H[it * DD + tid] = run;
        __threadfence();   // release H
    }
    __syncthreads();
    const unsigned int epoch1 = (unsigned int)(tick_s / NT) + 1u;
    if (tid == 0) atomicExch(&g_hflag[it], epoch1);

    // early non-blocking probe of predecessor flags (overlaps local work)
    unsigned int f0 = epoch1;
    if (tid < it) f0 = *(volatile unsigned int*)&g_hflag[tid];

    // ---- HOIST: cross-tile decay factors (independent of peers' H) ----
    float dec[NT - 1];
    if (tid < DD) {
        const int m = tid / D, kk = tid % D;
        const float b2 = b2s[kk * D + m];
#pragma unroll
        for (int s = 0; s < NT - 1; s++) {
            float tr = (s < it) ? trefs[s] : tref;   // pad: ex2(0)=1
            dec[s] = ex2(-b2 * (tref - tr));
        }
    }

    // ---- local work AFTER publish (F rows are thread-private: no barrier) ----
#pragma unroll
    for (int m = 0; m < D; m++)
        F[tid * PAD + m] = abt[ei * D + m] * ex2(-b2s[ei * D + m] * dtj);

    // in-warp strict triangle
    float tri = 0.f;
    {
        const int base = tid & ~31;
        const int lid  = tid & 31;
#pragma unroll
        for (int jj = 0; jj < 31; jj++) {
            if (jj < lid) {
                int j = base + jj;
                tri = fmaf(F[tid * PAD + es[j]], G[j * PAD + ei], tri);
            }
        }
    }

    // cross-sub-block (prefix at sb-1)
    float crossSub = 0.f;
    {
        const int sb = tid >> 5;
        if (sb > 0) {
#pragma unroll
            for (int m = 0; m < D; m++)
                crossSub = fmaf(F[tid * PAD + m], subH[sb - 1][m * D + ei], crossSub);
        }
    }

    // contrib term (independent of P)
    const float Tf = decodeT(Tp);
    const float dT = Tf - ti;
    float contrib = 0.f;
#pragma unroll
    for (int d = 0; d < D; d++)
        contrib += alphas[d * D + ei] * (1.f - ex2(-b2s[d * D + ei] * dT));

    // ---- spin on predecessors (only if the early probe missed) ----
    if (tid < it && f0 < epoch1) {
        while (*(volatile unsigned int*)&g_hflag[tid] < epoch1)
            __nanosleep(32);
    }
    __syncthreads();
    __threadfence();   // acquire H

    // ---- cross-tile P: batched 31 loads, pre-hoisted decays, 31 FMA ----
    if (tid < DD) {
        const int m = tid / D, kk = tid % D;
        float h[NT - 1];
#pragma unroll
        for (int s = 0; s < NT - 1; s++)
            h[s] = (s < it) ? __ldcg(&g_H[s * DD + tid]) : 0.f;
        float acc = 0.f;
#pragma unroll
        for (int s = 0; s < NT - 1; s++)
            acc = fmaf(h[s], dec[s], acc);
        Psm[m * PAD + kk] = acc;
    }
    __syncthreads();

    float crossTile = 0.f;
    if (it > 0) {
#pragma unroll
        for (int m = 0; m < D; m++)
            crossTile = fmaf(F[tid * PAD + m], Psm[m * PAD + ei], crossTile);
    }

    // ---- finalize per event: float in-warp, double across warps ----
    const float inten = mus[ei] + tri + crossSub + crossTile;
    float vf = __logf(inten) - contrib;
#pragma unroll
    for (int off = 16; off > 0; off >>= 1)
        vf += __shfl_down_sync(0xffffffffu, vf, off);
    if ((tid & 31) == 0) red[tid >> 5] = (double)vf;
    __syncthreads();

    if (tid == 0) {
        double bs = 0.0;
#pragma unroll
        for (int w = 0; w < NSB; w++) bs += red[w];
        long long q = __double2ll_rn(bs * 4294967296.0);
        atomicAdd((unsigned long long*)&g_sum, (unsigned long long)q);
        __threadfence();
        unsigned long long t2 = atomicAdd(&g_ctr2, 1ULL);
        if ((t2 % NT) == (NT - 1)) {
            __threadfence();
            long long tot = (long long)atomicExch((unsigned long long*)&g_sum, 0ULL);
            double s = (double)tot / 4294967296.0;
            double musum = 0.0;
#pragma unroll
            for (int d = 0; d < D; d++) musum += (double)mus[d];
            out[0] = (float)(s - musum * (double)Tf);
        }
    }
}

extern "C" void kernel_launch(void* const* d_in, const int* in_sizes, int n_in,
                              void* d_out, int out_size) {
    const float* t  = (const float*)d_in[0];
    const int*   et = (const int*)d_in[1];
    const float* mu = (const float*)d_in[2];
    const float* la = (const float*)d_in[3];
    const float* lb = (const float*)d_in[4];
    const int*   Tp = (const int*)d_in[5];

    hawkes_fused<<<NT, TILE>>>(t, et, mu, la, lb, Tp, (float*)d_out);
}